// round 1
// baseline (speedup 1.0000x reference)
#include <cuda_runtime.h>
#include <math.h>

#define NCTA 128
#define NTHR 512
#define BB   32
#define SS   512
#define HH   512
#define EE   512
#define KTOT 1024   // E + H
#define NKP  512    // KTOT / 2 (float2 pairs)
#define ROWS 16     // 4 gates * 4 j per CTA
#define JPB  4

// smem layout (bytes)
#define OFF_W     0         // 16*512 float2 = 65536
#define OFF_SEQ   65536     // 16384 int     = 65536
#define OFF_PART  131072    // 16*16*32 u64  = 65536
#define OFF_CONST 196608    // 16*32 float   = 2048
#define OFF_GSUM  198656    // 16*32 float   = 2048
#define OFF_C0    200704    // 4*32 float    = 512
#define OFF_HLOC  201216    // 4*32 float    = 512
#define OFF_MISC  201728
#define SMEM_BYTES 201792

// global scratch: double-buffered transposed h:  [buf][kp(=j/2)][b] as float2(u64)
__device__ unsigned long long g_ht2[2][256][BB];
__device__ unsigned g_bar_count;
__device__ unsigned g_bar_gen;

union F2U { unsigned long long u; float2 f; };

__device__ __forceinline__ unsigned long long ffma2u(unsigned long long a,
                                                     unsigned long long b,
                                                     unsigned long long c) {
#if defined(__CUDA_ARCH__) && __CUDA_ARCH__ >= 1000
    unsigned long long d;
    asm("fma.rn.f32x2 %0, %1, %2, %3;" : "=l"(d) : "l"(a), "l"(b), "l"(c));
    return d;
#else
    F2U A, Bv, C, D;
    A.u = a; Bv.u = b; C.u = c;
    D.f.x = fmaf(A.f.x, Bv.f.x, C.f.x);
    D.f.y = fmaf(A.f.y, Bv.f.y, C.f.y);
    return D.u;
#endif
}

__device__ __forceinline__ float sigmoidf_(float x) {
    return 1.0f / (1.0f + expf(-x));
}

__global__ __launch_bounds__(NTHR, 1)
void lstm_persistent_kernel(const int* __restrict__ seq,
                            const float* __restrict__ enc_h,
                            const float* __restrict__ enc_c,
                            const float* __restrict__ emb_table,
                            const float* __restrict__ W_ih,
                            const float* __restrict__ W_hh,
                            const float* __restrict__ b_ih,
                            const float* __restrict__ b_hh,
                            float* __restrict__ out)
{
    extern __shared__ char smem[];
    unsigned long long* w2_sh  = (unsigned long long*)(smem + OFF_W);
    int*                seq_sh = (int*)(smem + OFF_SEQ);
    unsigned long long* part   = (unsigned long long*)(smem + OFF_PART);
    float*              cns_sh = (float*)(smem + OFF_CONST);
    float*              gsum   = (float*)(smem + OFF_GSUM);
    float*              c0_sh  = (float*)(smem + OFF_C0);
    float*              h_loc  = (float*)(smem + OFF_HLOC);
    unsigned*           s_u    = (unsigned*)(smem + OFF_MISC);

    const int tid = threadIdx.x;
    const int bid = blockIdx.x;
    const int ks  = tid >> 5;   // 0..15 : k-split (warp id)
    const int b   = tid & 31;   // batch lane
    const int j0  = bid * JPB;

    if (tid == 0) s_u[0] = *(volatile unsigned*)&g_bar_gen;

    // ---- prologue: stage weights (as float2/u64), sequence (transposed), c0 ----
    for (int idx = tid; idx < ROWS * NKP; idx += NTHR) {
        int r = idx >> 9;            // row 0..15
        int kp = idx & (NKP - 1);
        int gate = r >> 2, jj = r & 3;
        int grow = gate * HH + j0 + jj;
        w2_sh[idx] = ((const unsigned long long*)(W_ih + (size_t)grow * KTOT))[kp];
    }
    for (int i = tid; i < BB * SS; i += NTHR) {
        int bb = i >> 9, tt = i & (SS - 1);
        seq_sh[tt * BB + bb] = seq[i];      // transposed: [t][b]
    }
    if (tid < 128) {
        int jj = ks;                        // 0..3
        c0_sh[jj * BB + b] = enc_c[b * HH + j0 + jj];
    }
    __syncthreads();

    // ---- const = h0 @ W_hh^T + b_ih + b_hh  (one-time, fp32 scalar) ----
    {
        float* partf = (float*)part;
        float h0c[32];
        #pragma unroll
        for (int i = 0; i < 32; i++) h0c[i] = enc_h[b * HH + ks * 32 + i];
        #pragma unroll
        for (int r = 0; r < ROWS; r++) {
            int gate = r >> 2, jj = r & 3;
            const float* wr = W_hh + (size_t)(gate * HH + j0 + jj) * HH + ks * 32;
            float acc = 0.f;
            #pragma unroll
            for (int i = 0; i < 32; i++) acc = fmaf(h0c[i], wr[i], acc);
            partf[(ks * ROWS + r) * BB + b] = acc;
        }
        __syncthreads();
        {
            int r2 = ks;
            float s = 0.f;
            #pragma unroll
            for (int k2 = 0; k2 < 16; k2++) s += partf[(k2 * ROWS + r2) * BB + b];
            int gate = r2 >> 2, jj = r2 & 3;
            int grow = gate * HH + j0 + jj;
            cns_sh[r2 * BB + b] = s + b_ih[grow] + b_hh[grow];
        }
        __syncthreads();
    }
    const unsigned gen0 = s_u[0];

    // ---- main sequential loop over time steps ----
    for (int t = 0; t < SS; t++) {
        unsigned long long x[32];

        // embedding half does not depend on h: issue loads BEFORE the barrier wait
        if (ks < 8) {
            int row = seq_sh[t * BB + b];
            const unsigned long long* er =
                (const unsigned long long*)(emb_table + (size_t)row * EE) + ks * 32;
            #pragma unroll
            for (int i = 0; i < 32; i++) x[i] = er[i];
        }

        if (t > 0) {
            if (tid == 0) {
                unsigned target = gen0 + (unsigned)t;
                while ((int)(*(volatile unsigned*)&g_bar_gen - target) < 0)
                    __nanosleep(64);
            }
            __syncthreads();
            if (ks >= 8) {
                const unsigned long long* hb = &g_ht2[(t - 1) & 1][(ks - 8) * 32][0];
                #pragma unroll
                for (int i = 0; i < 32; i++) x[i] = __ldcg(&hb[i * BB + b]);
            }
        } else {
            if (ks >= 8) {
                #pragma unroll
                for (int i = 0; i < 32; i++) x[i] = 0ull;   // h_{-1} = 0
            }
        }

        // ---- split-K partial dot products (f32x2 packed FMA) ----
        unsigned long long acc[ROWS];
        #pragma unroll
        for (int r = 0; r < ROWS; r++) acc[r] = 0ull;
        #pragma unroll
        for (int i = 0; i < 32; i++) {
            #pragma unroll
            for (int r = 0; r < ROWS; r++)
                acc[r] = ffma2u(x[i], w2_sh[r * NKP + ks * 32 + i], acc[r]);
        }
        #pragma unroll
        for (int r = 0; r < ROWS; r++)
            part[(ks * ROWS + r) * BB + b] = acc[r];
        __syncthreads();

        // ---- cross-warp reduction over ksplit ----
        {
            int r2 = ks;
            float sx = 0.f, sy = 0.f;
            #pragma unroll
            for (int k2 = 0; k2 < 16; k2++) {
                F2U p; p.u = part[(k2 * ROWS + r2) * BB + b];
                sx += p.f.x; sy += p.f.y;
            }
            gsum[r2 * BB + b] = sx + sy + cns_sh[r2 * BB + b];
        }
        __syncthreads();

        // ---- gate nonlinearities (128 threads: jj x b) ----
        if (tid < 128) {
            int jj = ks;   // 0..3
            float iv = gsum[(0 * 4 + jj) * BB + b];
            float fv = gsum[(1 * 4 + jj) * BB + b];
            float gv = gsum[(2 * 4 + jj) * BB + b];
            float ov = gsum[(3 * 4 + jj) * BB + b];
            float ig = sigmoidf_(iv);
            float fg = sigmoidf_(fv);
            float gg = tanhf(gv);
            float og = sigmoidf_(ov);
            float cc = fg * c0_sh[jj * BB + b] + ig * gg;
            float hh = og * tanhf(cc);
            h_loc[jj * BB + b] = hh;
        }
        __syncthreads();

        // ---- write output + transposed h scratch (double-buffered) ----
        if (tid < 32) {
            float4 o4 = make_float4(h_loc[0 * BB + tid], h_loc[1 * BB + tid],
                                    h_loc[2 * BB + tid], h_loc[3 * BB + tid]);
            *(float4*)(out + (size_t)tid * (SS * HH) + (size_t)t * HH + j0) = o4;
        } else if (tid < 96) {
            int p  = (tid - 32) >> 5;   // 0..1
            int bb = tid & 31;
            F2U hv;
            hv.f = make_float2(h_loc[(2 * p) * BB + bb], h_loc[(2 * p + 1) * BB + bb]);
            g_ht2[t & 1][bid * 2 + p][bb] = hv.u;
            __threadfence();
        }
        __syncthreads();

        // ---- grid barrier arrive ----
        if (tid == 0) {
            unsigned c = atomicAdd(&g_bar_count, 1u);
            if (c == NCTA - 1) {
                *(volatile unsigned*)&g_bar_count = 0u;
                __threadfence();
                *(volatile unsigned*)&g_bar_gen = gen0 + (unsigned)t + 1u;
            }
        }
    }
}

extern "C" void kernel_launch(void* const* d_in, const int* in_sizes, int n_in,
                              void* d_out, int out_size) {
    const int*   seq   = (const int*)d_in[0];
    // d_in[1] = enc_out : unused by the reference computation
    const float* enc_h = (const float*)d_in[2];
    const float* enc_c = (const float*)d_in[3];
    const float* emb   = (const float*)d_in[4];
    const float* W_ih  = (const float*)d_in[5];
    const float* W_hh  = (const float*)d_in[6];
    const float* b_ih  = (const float*)d_in[7];
    const float* b_hh  = (const float*)d_in[8];
    float* out = (float*)d_out;

    cudaFuncSetAttribute(lstm_persistent_kernel,
                         cudaFuncAttributeMaxDynamicSharedMemorySize, SMEM_BYTES);
    lstm_persistent_kernel<<<NCTA, NTHR, SMEM_BYTES>>>(
        seq, enc_h, enc_c, emb, W_ih, W_hh, b_ih, b_hh, out);
}